// round 4
// baseline (speedup 1.0000x reference)
#include <cuda_runtime.h>
#include <math.h>

#define T_  256
#define B_  32
#define E_  256
#define H_  512
#define V_  2048
#define TB_ 8192
#define G4H 2048

// ---------------- static device scratch ----------------
__device__ float g_X[TB_ * 512];                  // [t*B+b][512]
__device__ float g_G[(size_t)T_ * G4H * B_];      // [t][n][b]  (pure ih-dot, no bias)
__device__ float g_Y0[(size_t)TB_ * H_];
__device__ float g_Y1[(size_t)TB_ * H_];
__device__ float g_logits[(size_t)TB_ * V_];
__device__ float g_hbuf[2][2][H_][B_];            // [layer][ping][k][b]
__device__ float g_rowloss[TB_];
__device__ unsigned int g_bar[2];

// ---------------- XLA-matched fp32 nonlinearities ----------------
// XLA GPU tanh f32: |x| < 0.0004 -> x ; clamp to [-9,9]; Eigen rational approx,
// emitted as un-contracted mul/add chains.
__device__ __forceinline__ float xla_tanhf(float x) {
    float ax = fabsf(x);
    float xc = fminf(fmaxf(x, -9.0f), 9.0f);
    float x2 = __fmul_rn(xc, xc);
    float p = -2.76076847742355e-16f;
    p = __fadd_rn(__fmul_rn(p, x2),  2.00018790482477e-13f);
    p = __fadd_rn(__fmul_rn(p, x2), -8.60467152213735e-11f);
    p = __fadd_rn(__fmul_rn(p, x2),  5.12229709037114e-08f);
    p = __fadd_rn(__fmul_rn(p, x2),  1.48572235717979e-05f);
    p = __fadd_rn(__fmul_rn(p, x2),  6.37261928875436e-04f);
    p = __fadd_rn(__fmul_rn(p, x2),  4.89352455891786e-03f);
    float np = __fmul_rn(xc, p);
    float q = 1.19825839466702e-06f;
    q = __fadd_rn(__fmul_rn(q, x2),  1.18534705686654e-04f);
    q = __fadd_rn(__fmul_rn(q, x2),  2.26843463243900e-03f);
    q = __fadd_rn(__fmul_rn(q, x2),  4.89352518554385e-03f);
    float r = __fdiv_rn(np, q);
    return (ax < 0.0004f) ? x : r;
}
// XLA LogisticExpander: 1 / (1 + exp(-x)), all fp32 rn ops.
__device__ __forceinline__ float xla_sigmoidf(float x) {
    return __fdiv_rn(1.0f, __fadd_rn(1.0f, expf(-x)));
}

// ---------------- init ----------------
__global__ void init_kernel(const float* __restrict__ h0) {
    int idx = blockIdx.x * 256 + threadIdx.x;
    if (idx < 2) g_bar[idx] = 0u;
    if (idx < 2 * H_ * B_) {
        int l = idx >> 14;
        int rem = idx & 16383;
        int k = rem >> 5, b = rem & 31;
        g_hbuf[l][0][k][b] = h0[(size_t)l * B_ * H_ + (size_t)b * H_ + k];
    }
}

// ---------------- embedding gather ----------------
__global__ void embed_kernel(const int* __restrict__ pc, const int* __restrict__ delta,
                             const float* __restrict__ pc_emb, const float* __restrict__ delta_emb) {
    int r = blockIdx.x;
    int i = threadIdx.x;                         // 128 threads = 128 float4
    float4* dst = (float4*)(g_X + (size_t)r * 512);
    if (i < 64) dst[i] = ((const float4*)(pc_emb + (size_t)pc[r] * E_))[i];
    else        dst[i] = ((const float4*)(delta_emb + (size_t)delta[r] * E_))[i - 64];
}

// ---------------- ih GEMM: G[t][n][b] = A . W^T (no bias) ----------------
__global__ void __launch_bounds__(256) gemm_ih_kernel(int which, const float* __restrict__ W) {
    const float* __restrict__ A = which ? g_Y0 : g_X;
    __shared__ float As[16][132];
    __shared__ float Bs[16][132];
    int tid = threadIdx.x;
    int tx = tid & 15, ty = tid >> 4;
    int bn = blockIdx.x * 128;
    int bm = blockIdx.y * 128;

    float acc[8][8];
#pragma unroll
    for (int i = 0; i < 8; i++)
#pragma unroll
        for (int j = 0; j < 8; j++) acc[i][j] = 0.0f;

    for (int k0 = 0; k0 < 512; k0 += 16) {
#pragma unroll
        for (int i = 0; i < 2; i++) {
            int f = tid + i * 256;
            int row = f >> 2;
            int c4 = (f & 3) * 4;
            float4 av = *(const float4*)(A + (size_t)(bm + row) * 512 + k0 + c4);
            As[c4 + 0][row] = av.x; As[c4 + 1][row] = av.y;
            As[c4 + 2][row] = av.z; As[c4 + 3][row] = av.w;
            float4 bv = *(const float4*)(W + (size_t)(bn + row) * 512 + k0 + c4);
            Bs[c4 + 0][row] = bv.x; Bs[c4 + 1][row] = bv.y;
            Bs[c4 + 2][row] = bv.z; Bs[c4 + 3][row] = bv.w;
        }
        __syncthreads();
#pragma unroll
        for (int kk = 0; kk < 16; kk++) {
            float4 a0 = *(const float4*)&As[kk][ty * 8];
            float4 a1 = *(const float4*)&As[kk][ty * 8 + 4];
            float4 q0 = *(const float4*)&Bs[kk][tx * 8];
            float4 q1 = *(const float4*)&Bs[kk][tx * 8 + 4];
            float am[8] = {a0.x, a0.y, a0.z, a0.w, a1.x, a1.y, a1.z, a1.w};
            float bb[8] = {q0.x, q0.y, q0.z, q0.w, q1.x, q1.y, q1.z, q1.w};
#pragma unroll
            for (int mi = 0; mi < 8; mi++)
#pragma unroll
                for (int nj = 0; nj < 8; nj++)
                    acc[mi][nj] = fmaf(am[mi], bb[nj], acc[mi][nj]);
        }
        __syncthreads();
    }

    int m0 = bm + ty * 8;
    int t = m0 >> 5;
    int b0 = m0 & 31;
#pragma unroll
    for (int nj = 0; nj < 8; nj++) {
        int n = bn + tx * 8 + nj;
        size_t base = ((size_t)t * G4H + n) * B_ + b0;
        float4 v0 = make_float4(acc[0][nj], acc[1][nj], acc[2][nj], acc[3][nj]);
        float4 v1 = make_float4(acc[4][nj], acc[5][nj], acc[6][nj], acc[7][nj]);
        *(float4*)(g_G + base) = v0;
        *(float4*)(g_G + base + 4) = v1;
    }
}

// ---------------- persistent LSTM layer (128 CTAs, grid barrier per step) ----------------
__global__ void __launch_bounds__(256) lstm_kernel(const float* __restrict__ Whh,
                                                   const float* __restrict__ c0l,
                                                   int layer, float* __restrict__ Y,
                                                   float* __restrict__ dout,
                                                   const float* __restrict__ bih,
                                                   const float* __restrict__ bhh) {
    extern __shared__ float sm[];
    float* h_s = sm;                 // 16384
    float* w_s = sm + 16384;         // 8192 : 16 rows (hl*4+g) x 512
    float* ex  = sm + 24576;         // 256  : [hjl*32+b]*2
    float* c_s = sm + 24832;         // 128

    float* hbuf = &g_hbuf[layer][0][0][0];
    unsigned int* bar = &g_bar[layer];

    int tid = threadIdx.x;
    int b = tid & 31, q = tid >> 5;
    int hjl = q & 3;
    int hj = blockIdx.x * 4 + hjl;
    int gbase = (q < 4) ? 0 : 2;     // gates (i,f) or (g,o)

    for (int i = tid; i < 2048; i += 256) {      // 2048 float4 of W_hh slice
        int r = i >> 7;
        int c4 = (i & 127) * 4;
        int g = r & 3, hl = r >> 2;
        *(float4*)(w_s + r * 512 + c4) =
            *(const float4*)(Whh + ((size_t)g * 512 + blockIdx.x * 4 + hl) * 512 + c4);
    }
    if (tid < 128) {
        int hl = tid >> 5, bb = tid & 31;
        c_s[hl * 32 + bb] = c0l[(size_t)bb * 512 + blockIdx.x * 4 + hl];
    }
    const float* w0 = w_s + (hjl * 4 + gbase) * 512;
    const float* w1 = w0 + 512;
    // bias sums, fp32 like ref: b_ih + b_hh
    int n0g = gbase * 512 + hj;
    int n1g = (gbase + 1) * 512 + hj;
    float bias0 = __fadd_rn(bih[n0g], bhh[n0g]);
    float bias1 = __fadd_rn(bih[n1g], bhh[n1g]);
    __syncthreads();

    int ping = 0;
    for (int t = 0; t < 256; t++) {
        const float* hsrc = hbuf + ping * 16384;
        for (int i = tid * 4; i < 16384; i += 1024)
            *(float4*)(h_s + i) = *(const float4*)(hsrc + i);
        __syncthreads();

        // hh-dot accumulated standalone from 0 (matches ref's separate GEMM)
        float acc0 = 0.0f, acc1 = 0.0f;
#pragma unroll 4
        for (int k = 0; k < 512; k += 4) {
            float4 wa = *(const float4*)(w0 + k);
            float4 wb = *(const float4*)(w1 + k);
            float h0v = h_s[(k + 0) * 32 + b];
            float h1v = h_s[(k + 1) * 32 + b];
            float h2v = h_s[(k + 2) * 32 + b];
            float h3v = h_s[(k + 3) * 32 + b];
            acc0 = fmaf(h0v, wa.x, acc0); acc1 = fmaf(h0v, wb.x, acc1);
            acc0 = fmaf(h1v, wa.y, acc0); acc1 = fmaf(h1v, wb.y, acc1);
            acc0 = fmaf(h2v, wa.z, acc0); acc1 = fmaf(h2v, wb.z, acc1);
            acc0 = fmaf(h3v, wa.w, acc0); acc1 = fmaf(h3v, wb.w, acc1);
        }

        // gates = (dot_ih + dot_hh) + bias, exact ref association
        float G0 = g_G[((size_t)t * G4H + n0g) * B_ + b];
        float G1 = g_G[((size_t)t * G4H + n1g) * B_ + b];
        float pre0 = __fadd_rn(__fadd_rn(G0, acc0), bias0);
        float pre1 = __fadd_rn(__fadd_rn(G1, acc1), bias1);

        if (q >= 4) {                 // g, o pre-activations
            ex[(hjl * 32 + b) * 2 + 0] = pre0;
            ex[(hjl * 32 + b) * 2 + 1] = pre1;
        }
        __syncthreads();
        if (q < 4) {                  // i=pre0, f=pre1
            float pre_g = ex[(hjl * 32 + b) * 2 + 0];
            float pre_o = ex[(hjl * 32 + b) * 2 + 1];
            float ig = xla_sigmoidf(pre0);
            float fg = xla_sigmoidf(pre1);
            float tg = xla_tanhf(pre_g);
            float og = xla_sigmoidf(pre_o);
            float cold = c_s[hjl * 32 + b];
            float cn = __fadd_rn(__fmul_rn(fg, cold), __fmul_rn(ig, tg));
            float hn = __fmul_rn(og, xla_tanhf(cn));
            c_s[hjl * 32 + b] = cn;
            hbuf[(ping ^ 1) * 16384 + hj * 32 + b] = hn;
            Y[((size_t)t * 32 + b) * 512 + hj] = hn;
            if (t == 255) {
                dout[81921  + (size_t)layer * 16384 + (size_t)b * 512 + hj] = hn;
                dout[114689 + (size_t)layer * 16384 + (size_t)b * 512 + hj] = cn;
            }
        }
        // grid barrier
        __syncthreads();
        if (tid == 0) {
            __threadfence();
            atomicAdd(bar, 1u);
            unsigned int target = 128u * (unsigned)(t + 1);
            volatile unsigned int* vb = (volatile unsigned int*)bar;
            while (*vb < target) { }
            __threadfence();
        }
        __syncthreads();
        ping ^= 1;
    }
}

// ---------------- cluster-routed projection: logits[t][b][v] ----------------
__global__ void __launch_bounds__(256) logits_kernel(const int* __restrict__ clusters,
                                                     const float* __restrict__ Wc,
                                                     const float* __restrict__ bc) {
    __shared__ float As[32][36];
    __shared__ float Bs[32][132];
    int tid = threadIdx.x;
    int t = blockIdx.y;
    int c = clusters[t];
    int n0 = blockIdx.x * 128;
    int tm = tid >> 5, tn = tid & 31;

    float acc[4][4];
#pragma unroll
    for (int i = 0; i < 4; i++)
#pragma unroll
        for (int j = 0; j < 4; j++) acc[i][j] = 0.0f;

    for (int k0 = 0; k0 < 512; k0 += 32) {
        {
            int m = tid >> 3, kq = tid & 7;
            float4 av = *(const float4*)(g_Y1 + ((size_t)t * 32 + m) * 512 + k0 + kq * 4);
            As[kq * 4 + 0][m] = av.x; As[kq * 4 + 1][m] = av.y;
            As[kq * 4 + 2][m] = av.z; As[kq * 4 + 3][m] = av.w;
        }
#pragma unroll
        for (int i = 0; i < 4; i++) {
            int idx = tid + i * 256;
            int kk = idx >> 5, c4 = (idx & 31) * 4;
            float4 bv = *(const float4*)(Wc + ((size_t)c * 512 + k0 + kk) * 2048 + n0 + c4);
            *(float4*)&Bs[kk][c4] = bv;
        }
        __syncthreads();
#pragma unroll
        for (int kk = 0; kk < 32; kk++) {
            float4 a = *(const float4*)&As[kk][tm * 4];
            float4 bq = *(const float4*)&Bs[kk][tn * 4];
            float am[4] = {a.x, a.y, a.z, a.w};
            float bb[4] = {bq.x, bq.y, bq.z, bq.w};
#pragma unroll
            for (int mi = 0; mi < 4; mi++)
#pragma unroll
                for (int nj = 0; nj < 4; nj++)
                    acc[mi][nj] = fmaf(am[mi], bb[nj], acc[mi][nj]);
        }
        __syncthreads();
    }
#pragma unroll
    for (int mi = 0; mi < 4; mi++) {
        int row = t * 32 + tm * 4 + mi;
        int col = n0 + tn * 4;
        float4 bv = *(const float4*)(bc + (size_t)c * 2048 + col);
        float4 v = make_float4(__fadd_rn(acc[mi][0], bv.x), __fadd_rn(acc[mi][1], bv.y),
                               __fadd_rn(acc[mi][2], bv.z), __fadd_rn(acc[mi][3], bv.w));
        *(float4*)(g_logits + (size_t)row * 2048 + col) = v;
    }
}

// ---------------- log-softmax + loss + top-10 per row ----------------
// Ranking key replicates ref exactly: fl32( fl32(v - M) - logS ).
__global__ void __launch_bounds__(256) softmax_topk_kernel(const int* __restrict__ target,
                                                           float* __restrict__ dout) {
    int r = blockIdx.x;
    int tid = threadIdx.x;
    const float* L = g_logits + (size_t)r * 2048;
    float v[8];
#pragma unroll
    for (int j = 0; j < 8; j++) v[j] = L[tid + j * 256];

    __shared__ float  sv[8];
    __shared__ int    si[8];
    __shared__ double sd[8];
    __shared__ float  sbc;

    // exact fp32 max
    float m = -INFINITY;
#pragma unroll
    for (int j = 0; j < 8; j++) m = fmaxf(m, v[j]);
#pragma unroll
    for (int o = 16; o > 0; o >>= 1) m = fmaxf(m, __shfl_xor_sync(0xffffffffu, m, o));
    if ((tid & 31) == 0) sv[tid >> 5] = m;
    __syncthreads();
    if (tid == 0) {
        float mm = sv[0];
        for (int w = 1; w < 8; w++) mm = fmaxf(mm, sv[w]);
        sv[0] = mm;
    }
    __syncthreads();
    float M = sv[0];

    // shifted in fp32 (ref bit pattern), sum of exp(shifted) in double
    float sf[8];
    double s = 0.0;
#pragma unroll
    for (int j = 0; j < 8; j++) {
        sf[j] = __fadd_rn(v[j], -M);
        s += exp((double)sf[j]);
    }
#pragma unroll
    for (int o = 16; o > 0; o >>= 1) s += __shfl_xor_sync(0xffffffffu, s, o);
    if ((tid & 31) == 0) sd[tid >> 5] = s;
    __syncthreads();
    if (tid == 0) {
        double ss = 0.0;
        for (int w = 0; w < 8; w++) ss += sd[w];
        double logS = log(ss);
        sbc = (float)logS;
        float sft = __fadd_rn(L[target[r]], -M);
        g_rowloss[r] = (float)(logS - (double)sft);
    }
    __syncthreads();
    float logS_f = sbc;

    // qv = fl(shifted - logS): binade-uniform grid -> ranking invariant to ulp-level logS diff
    float qv[8];
#pragma unroll
    for (int j = 0; j < 8; j++) qv[j] = __fadd_rn(sf[j], -logS_f);

    // iterative top-10, ties -> lowest index (jax top_k)
    for (int it = 0; it < 10; it++) {
        float bv = -INFINITY;
        int bi = 1 << 30;
#pragma unroll
        for (int j = 0; j < 8; j++) {
            int gi = tid + j * 256;
            if (qv[j] > bv || (qv[j] == bv && gi < bi)) { bv = qv[j]; bi = gi; }
        }
#pragma unroll
        for (int o = 16; o > 0; o >>= 1) {
            float ov = __shfl_xor_sync(0xffffffffu, bv, o);
            int   oi = __shfl_xor_sync(0xffffffffu, bi, o);
            if (ov > bv || (ov == bv && oi < bi)) { bv = ov; bi = oi; }
        }
        if ((tid & 31) == 0) { sv[tid >> 5] = bv; si[tid >> 5] = bi; }
        __syncthreads();
        if (tid == 0) {
            float wv = sv[0]; int wi = si[0];
            for (int w = 1; w < 8; w++)
                if (sv[w] > wv || (sv[w] == wv && si[w] < wi)) { wv = sv[w]; wi = si[w]; }
            si[0] = wi;
            dout[1 + (size_t)r * 10 + it] = (float)wi;
        }
        __syncthreads();
        int wi = si[0];
        if ((wi & 255) == tid) qv[wi >> 8] = -INFINITY;
        __syncthreads();
    }
}

// ---------------- deterministic loss reduction (double) ----------------
__global__ void __launch_bounds__(256) loss_kernel(float* __restrict__ dout) {
    __shared__ double s[256];
    int tid = threadIdx.x;
    double a = 0.0;
    for (int i = 0; i < 32; i++) a += (double)g_rowloss[tid * 32 + i];
    s[tid] = a;
    __syncthreads();
    for (int o = 128; o > 0; o >>= 1) {
        if (tid < o) s[tid] += s[tid + o];
        __syncthreads();
    }
    if (tid == 0) dout[0] = (float)(s[0] / 8192.0);
}

extern "C" void kernel_launch(void* const* d_in, const int* in_sizes, int n_in,
                              void* d_out, int out_size) {
    const int*   pc        = (const int*)d_in[0];
    const int*   delta     = (const int*)d_in[1];
    const int*   clusters  = (const int*)d_in[2];
    const int*   target    = (const int*)d_in[3];
    const float* h0        = (const float*)d_in[4];
    const float* c0        = (const float*)d_in[5];
    const float* pc_emb    = (const float*)d_in[6];
    const float* delta_emb = (const float*)d_in[7];
    const float* w_ih0     = (const float*)d_in[8];
    const float* w_hh0     = (const float*)d_in[9];
    const float* b_ih0     = (const float*)d_in[10];
    const float* b_hh0     = (const float*)d_in[11];
    const float* w_ih1     = (const float*)d_in[12];
    const float* w_hh1     = (const float*)d_in[13];
    const float* b_ih1     = (const float*)d_in[14];
    const float* b_hh1     = (const float*)d_in[15];
    const float* Wc        = (const float*)d_in[16];
    const float* bc        = (const float*)d_in[17];
    float* out = (float*)d_out;

    static int smem_set = 0;
    int lstm_smem = 24960 * 4;
    if (!smem_set) {
        cudaFuncSetAttribute(lstm_kernel, cudaFuncAttributeMaxDynamicSharedMemorySize, lstm_smem);
        smem_set = 1;
    }

    float* g_Y0p = nullptr; float* g_Y1p = nullptr;
    cudaGetSymbolAddress((void**)&g_Y0p, g_Y0);
    cudaGetSymbolAddress((void**)&g_Y1p, g_Y1);

    init_kernel<<<128, 256>>>(h0);
    embed_kernel<<<TB_, 128>>>(pc, delta, pc_emb, delta_emb);
    gemm_ih_kernel<<<dim3(16, 64), 256>>>(0, w_ih0);
    lstm_kernel<<<128, 256, lstm_smem>>>(w_hh0, c0, 0, g_Y0p, out, b_ih0, b_hh0);
    gemm_ih_kernel<<<dim3(16, 64), 256>>>(1, w_ih1);
    lstm_kernel<<<128, 256, lstm_smem>>>(w_hh1, c0 + (size_t)B_ * H_, 1, g_Y1p, out, b_ih1, b_hh1);
    logits_kernel<<<dim3(16, 256), 256>>>(clusters, Wc, bc);
    softmax_topk_kernel<<<TB_, 256>>>(target, out);
    loss_kernel<<<1, 256>>>(out);
}